// round 10
// baseline (speedup 1.0000x reference)
#include <cuda_runtime.h>

#define HH   512
#define WW   512
#define HWSZ (HH * WW)
#define CIN  32
#define COUT 24
#define NP   8

typedef unsigned long long u64;

__device__ __forceinline__ u64 fma2_(u64 a, u64 b, u64 c) {
    u64 d; asm("fma.rn.f32x2 %0, %1, %2, %3;" : "=l"(d) : "l"(a), "l"(b), "l"(c)); return d;
}
__device__ __forceinline__ u64 add2_(u64 a, u64 b) {
    u64 d; asm("add.rn.f32x2 %0, %1, %2;" : "=l"(d) : "l"(a), "l"(b)); return d;
}
__device__ __forceinline__ u64 mul2_(u64 a, u64 b) {
    u64 d; asm("mul.rn.f32x2 %0, %1, %2;" : "=l"(d) : "l"(a), "l"(b)); return d;
}
__device__ __forceinline__ u64 pack2_(float lo, float hi) {
    u64 r; asm("mov.b64 %0, {%1, %2};" : "=l"(r) : "f"(lo), "f"(hi)); return r;
}
__device__ __forceinline__ float2 unpack2_(u64 v) {
    float lo, hi; asm("mov.b64 {%0, %1}, %2;" : "=f"(lo), "=f"(hi) : "l"(v));
    return make_float2(lo, hi);
}

#define M1C 0xBF800000BF800000ull   /* (-1.0f, -1.0f) */

// Packed exp(-d2) computed ENTIRELY on the FMA/ALU pipes (no MUFU):
//   y = -d2*log2(e) clamped to >= -126
//   n = rint(y) via RN magic-number; f = y - n in [-0.5, 0.5]
//   2^f by degree-5 Taylor (rel err ~2e-6); scale by 2^n via exponent insert.
// The MUFU pipe (26M EX2 ops otherwise) is the hidden wall of prior rounds.
__device__ __forceinline__ u64 wexp2_(u64 d2pair) {
    const float L2E = 1.4426950408889634f;
    float2 d = unpack2_(d2pair);
    float y0 = fmaxf(d.x * -L2E, -126.0f);
    float y1 = fmaxf(d.y * -L2E, -126.0f);
    u64 y = pack2_(y0, y1);
    u64 t = add2_(y, pack2_(12582912.0f, 12582912.0f));     // RN magic add
    float2 tf = unpack2_(t);
    int n0 = __float_as_int(tf.x) - 0x4B400000;             // integer part
    int n1 = __float_as_int(tf.y) - 0x4B400000;
    u64 nf = add2_(t, pack2_(-12582912.0f, -12582912.0f));  // float(n)
    u64 f  = fma2_(nf, M1C, y);                             // y - n
    // 2^f, Horner degree-5 (Taylor of e^{f ln2})
    u64 p = pack2_(1.3333558146e-3f, 1.3333558146e-3f);
    p = fma2_(p, f, pack2_(9.6181291076e-3f, 9.6181291076e-3f));
    p = fma2_(p, f, pack2_(5.5504108665e-2f, 5.5504108665e-2f));
    p = fma2_(p, f, pack2_(2.4022650696e-1f, 2.4022650696e-1f));
    p = fma2_(p, f, pack2_(6.9314718056e-1f, 6.9314718056e-1f));
    p = fma2_(p, f, pack2_(1.0f, 1.0f));
    float2 pf = unpack2_(p);
    float w0 = __int_as_float(__float_as_int(pf.x) + (n0 << 23));
    float w1 = __int_as_float(__float_as_int(pf.y) + (n1 << 23));
    return pack2_(w0, w1);
}

// R6 structure verbatim (best: 98.8us): fused single pass, dy fully unrolled,
// 3-load aligned window, branch-free masks, normalize at store, 255 regs.
// Only change: __expf -> wexp2_ (MUFU -> FMA/ALU pipes).
__global__ void __launch_bounds__(128) bilat_kernel(
    const float* __restrict__ inp, const float* __restrict__ par,
    float* __restrict__ out)
{
    const int lane = threadIdx.x & 31;
    const int ty   = threadIdx.x >> 5;
    const int x0   = blockIdx.x * 128 + lane * 4;
    const int y    = blockIdx.y * 4 + ty;
    const int b    = blockIdx.z;

    const float* __restrict__ parb = par + b * (NP * HWSZ);
    const float* __restrict__ inpb = inp + b * (CIN * HWSZ);
    float* __restrict__ outb = out + b * (COUT * HWSZ);

    const int xa = max(x0 - 4, 0);
    const int xb = x0;
    const int xc = min(x0 + 4, WW - 4);

    const int cbase = y * WW + x0;

    u64 mX[5][2];
#pragma unroll
    for (int dx = 0; dx < 5; ++dx) {
        const int g = x0 + dx * 2 - 4;
        mX[dx][0] = pack2_(((unsigned)(g + 0) < (unsigned)WW) ? 1.0f : 0.0f,
                           ((unsigned)(g + 1) < (unsigned)WW) ? 1.0f : 0.0f);
        mX[dx][1] = pack2_(((unsigned)(g + 2) < (unsigned)WW) ? 1.0f : 0.0f,
                           ((unsigned)(g + 3) < (unsigned)WW) ? 1.0f : 0.0f);
    }

    u64 acc[COUT][2];
#pragma unroll
    for (int c = 0; c < COUT; ++c) { acc[c][0] = 0ull; acc[c][1] = 0ull; }
    u64 ws0 = 0ull, ws1 = 0ull;

#pragma unroll
    for (int dy = 0; dy < 5; ++dy) {
        const int   ny = y + dy * 2 - 4;
        const float mr = ((unsigned)ny < (unsigned)HH) ? 1.0f : 0.0f;
        const int   ro = min(max(ny, 0), HH - 1) * WW;

        u64 d2[5][2];
#pragma unroll
        for (int dx = 0; dx < 5; ++dx) { d2[dx][0] = 0ull; d2[dx][1] = 0ull; }

#pragma unroll
        for (int p = 0; p < NP; ++p) {
            const float* pr = parb + p * HWSZ;
            ulonglong2 cc = __ldg(reinterpret_cast<const ulonglong2*>(pr + cbase));
            ulonglong2 l0 = __ldg(reinterpret_cast<const ulonglong2*>(pr + ro + xa));
            ulonglong2 l1 = __ldg(reinterpret_cast<const ulonglong2*>(pr + ro + xb));
            ulonglong2 l2 = __ldg(reinterpret_cast<const ulonglong2*>(pr + ro + xc));
            u64 vp[6] = { l0.x, l0.y, l1.x, l1.y, l2.x, l2.y };
#pragma unroll
            for (int dx = 0; dx < 5; ++dx) {
                u64 t0 = fma2_(vp[dx],     M1C, cc.x);
                u64 t1 = fma2_(vp[dx + 1], M1C, cc.y);
                d2[dx][0] = fma2_(t0, t0, d2[dx][0]);
                d2[dx][1] = fma2_(t1, t1, d2[dx][1]);
            }
        }

        u64 w[5][2];
        const u64 mrow = pack2_(mr, mr);
#pragma unroll
        for (int dx = 0; dx < 5; ++dx) {
            u64 e0 = mul2_(wexp2_(d2[dx][0]), mul2_(mX[dx][0], mrow));
            u64 e1 = mul2_(wexp2_(d2[dx][1]), mul2_(mX[dx][1], mrow));
            w[dx][0] = e0;
            w[dx][1] = e1;
            ws0 = add2_(ws0, e0);
            ws1 = add2_(ws1, e1);
        }

#pragma unroll
        for (int ch = 0; ch < COUT; ++ch) {
            const float* ir = inpb + ch * HWSZ + ro;
            ulonglong2 l0 = __ldg(reinterpret_cast<const ulonglong2*>(ir + xa));
            ulonglong2 l1 = __ldg(reinterpret_cast<const ulonglong2*>(ir + xb));
            ulonglong2 l2 = __ldg(reinterpret_cast<const ulonglong2*>(ir + xc));
            u64 vp[6] = { l0.x, l0.y, l1.x, l1.y, l2.x, l2.y };
#pragma unroll
            for (int dx = 0; dx < 5; ++dx) {
                acc[ch][0] = fma2_(w[dx][0], vp[dx],     acc[ch][0]);
                acc[ch][1] = fma2_(w[dx][1], vp[dx + 1], acc[ch][1]);
            }
        }
    }

    float2 s0 = unpack2_(ws0), s1 = unpack2_(ws1);
    const u64 r0 = pack2_(__fdividef(1.0f, s0.x + 1e-8f),
                          __fdividef(1.0f, s0.y + 1e-8f));
    const u64 r1 = pack2_(__fdividef(1.0f, s1.x + 1e-8f),
                          __fdividef(1.0f, s1.y + 1e-8f));

#pragma unroll
    for (int ch = 0; ch < COUT; ++ch) {
        float2 f0 = unpack2_(mul2_(acc[ch][0], r0));
        float2 f1 = unpack2_(mul2_(acc[ch][1], r1));
        *reinterpret_cast<float4*>(outb + ch * HWSZ + cbase) =
            make_float4(f0.x, f0.y, f1.x, f1.y);
    }
}

extern "C" void kernel_launch(void* const* d_in, const int* in_sizes, int n_in,
                              void* d_out, int out_size)
{
    const float* inp = (const float*)d_in[0];   // (4,32,512,512) f32
    const float* par = (const float*)d_in[1];   // (4, 8,512,512) f32
    if (n_in >= 2 && in_sizes[0] < in_sizes[1]) {
        const float* t = inp; inp = par; par = t;
    }
    float* out = (float*)d_out;                 // (4,24,512,512) f32

    dim3 grid(WW / 128, HH / 4, 4);
    dim3 block(128);
    bilat_kernel<<<grid, block>>>(inp, par, out);
}